// round 2
// baseline (speedup 1.0000x reference)
#include <cuda_runtime.h>
#include <math_constants.h>

// Problem shape (fixed by the dataset): B=64, N=4096, D2=128, S=512
#define D2 128
#define MAXB 64
#define MAXN 4096

// Scratch (no cudaMalloc allowed)
__device__ float g_q[MAXB * D2];          // 32 KB
__device__ float g_logits[MAXB * MAXN];   // 1 MB

// ---------------------------------------------------------------------------
// K1: q[b,d] = sum_e yq[b,e] * w[e,d]
// grid = B, block = D2
// ---------------------------------------------------------------------------
__global__ void qproj_kernel(const float* __restrict__ yq,
                             const float* __restrict__ w) {
    __shared__ float syq[D2];
    const int b = blockIdx.x;
    const int d = threadIdx.x;
    syq[d] = yq[b * D2 + d];
    __syncthreads();
    float acc = 0.f;
#pragma unroll 8
    for (int e = 0; e < D2; e++) {
        acc = fmaf(syq[e], w[e * D2 + d], acc);
    }
    g_q[b * D2 + d] = acc;
}

// ---------------------------------------------------------------------------
// K2: logits[b,n] = q[b] . y_past[b,n]
// One warp handles 4 consecutive rows; each lane reads one float4 per row
// (512B contiguous per warp per row -> perfectly coalesced HBM stream).
// grid = (N/32, B), block = 256 (8 warps * 4 rows = 32 rows/block)
// ---------------------------------------------------------------------------
__global__ void logits_kernel(const float* __restrict__ y_past, int N) {
    const int b = blockIdx.y;
    __shared__ float sq[D2];
    if (threadIdx.x < D2) sq[threadIdx.x] = g_q[b * D2 + threadIdx.x];
    __syncthreads();

    const int warp = threadIdx.x >> 5;
    const int lane = threadIdx.x & 31;
    const int row0 = blockIdx.x * 32 + warp * 4;

    const float4* __restrict__ base =
        reinterpret_cast<const float4*>(y_past + (size_t)b * N * D2);
    const float4 qv = reinterpret_cast<const float4*>(sq)[lane];

    // Front-batch the 4 independent row loads for MLP
    float4 v0 = base[(size_t)(row0 + 0) * 32 + lane];
    float4 v1 = base[(size_t)(row0 + 1) * 32 + lane];
    float4 v2 = base[(size_t)(row0 + 2) * 32 + lane];
    float4 v3 = base[(size_t)(row0 + 3) * 32 + lane];

    float a0 = fmaf(v0.x, qv.x, fmaf(v0.y, qv.y, fmaf(v0.z, qv.z, v0.w * qv.w)));
    float a1 = fmaf(v1.x, qv.x, fmaf(v1.y, qv.y, fmaf(v1.z, qv.z, v1.w * qv.w)));
    float a2 = fmaf(v2.x, qv.x, fmaf(v2.y, qv.y, fmaf(v2.z, qv.z, v2.w * qv.w)));
    float a3 = fmaf(v3.x, qv.x, fmaf(v3.y, qv.y, fmaf(v3.z, qv.z, v3.w * qv.w)));

#pragma unroll
    for (int o = 16; o; o >>= 1) {
        a0 += __shfl_xor_sync(0xffffffffu, a0, o);
        a1 += __shfl_xor_sync(0xffffffffu, a1, o);
        a2 += __shfl_xor_sync(0xffffffffu, a2, o);
        a3 += __shfl_xor_sync(0xffffffffu, a3, o);
    }
    if (lane == 0) {
        float* dst = g_logits + (size_t)b * N + row0;
        dst[0] = a0; dst[1] = a1; dst[2] = a2; dst[3] = a3;
    }
}

// ---------------------------------------------------------------------------
// K3: per-batch softmax over N logits + scatter-add into S bins, normalize.
// grid = B, block = 512, dynamic smem = S floats (bins)
// ---------------------------------------------------------------------------
__global__ void softmax_scatter_kernel(const int* __restrict__ s_past,
                                       float* __restrict__ out,
                                       int N, int S) {
    extern __shared__ float bins[];          // S floats
    __shared__ float red[32];
    __shared__ float bcast;

    const int b = blockIdx.x;
    const int t = threadIdx.x;
    const int T = blockDim.x;                // 512
    const int per = N / T;                   // 8

    // Zero bins
    for (int s = t; s < S; s += T) bins[s] = 0.f;

    // Load logits into registers, find max
    float vals[32];
    float mx = -CUDART_INF_F;
    for (int i = 0; i < per; i++) {
        vals[i] = g_logits[(size_t)b * N + t + i * T];
        mx = fmaxf(mx, vals[i]);
    }
    // block-reduce max
#pragma unroll
    for (int o = 16; o; o >>= 1) mx = fmaxf(mx, __shfl_xor_sync(0xffffffffu, mx, o));
    if ((t & 31) == 0) red[t >> 5] = mx;
    __syncthreads();
    if (t < 32) {
        float m = (t < T / 32) ? red[t] : -CUDART_INF_F;
#pragma unroll
        for (int o = 16; o; o >>= 1) m = fmaxf(m, __shfl_xor_sync(0xffffffffu, m, o));
        if (t == 0) bcast = m;
    }
    __syncthreads();
    mx = bcast;

    // exp, local sum, scatter into shared bins
    float sum = 0.f;
    for (int i = 0; i < per; i++) {
        float e = expf(vals[i] - mx);
        sum += e;
        int sid = s_past[(size_t)b * N + t + i * T];
        atomicAdd(&bins[sid], e);
    }
    __syncthreads();   // also orders bin writes before the read below

    // block-reduce sum
#pragma unroll
    for (int o = 16; o; o >>= 1) sum += __shfl_xor_sync(0xffffffffu, sum, o);
    if ((t & 31) == 0) red[t >> 5] = sum;
    __syncthreads();
    if (t < 32) {
        float s2 = (t < T / 32) ? red[t] : 0.f;
#pragma unroll
        for (int o = 16; o; o >>= 1) s2 += __shfl_xor_sync(0xffffffffu, s2, o);
        if (t == 0) bcast = s2;
    }
    __syncthreads();
    const float inv_z = 1.0f / bcast;

    for (int s = t; s < S; s += T) {
        out[(size_t)b * S + s] = bins[s] * inv_z;
    }
}

// ---------------------------------------------------------------------------
// kernel_launch
// Inputs (metadata order): s_past (int32, B*N), yq (f32, B*D2),
//                          y_past (f32, B*N*D2), w_mat (f32, D2*D2),
//                          size_s (int scalar, on device)
// Output: post_est (f32, B*S)
// ---------------------------------------------------------------------------
extern "C" void kernel_launch(void* const* d_in, const int* in_sizes, int n_in,
                              void* d_out, int out_size) {
    const int*   s_past = (const int*)d_in[0];
    const float* yq     = (const float*)d_in[1];
    const float* y_past = (const float*)d_in[2];
    const float* w_mat  = (const float*)d_in[3];
    float*       out    = (float*)d_out;

    const int D = D2;                       // 128 (w_mat is D2 x D2)
    const int B = in_sizes[1] / D;          // 64
    const int N = in_sizes[0] / B;          // 4096
    const int S = out_size / B;             // 512

    qproj_kernel<<<B, D>>>(yq, w_mat);

    dim3 grid2(N / 32, B);
    logits_kernel<<<grid2, 256>>>(y_past, N);

    softmax_scatter_kernel<<<B, 512, S * sizeof(float)>>>(s_past, out, N, S);
}

// round 3
// speedup vs baseline: 1.2538x; 1.2538x over previous
#include <cuda_runtime.h>
#include <math_constants.h>

// Problem shape (fixed by the dataset): B=64, N=4096, D2=128, S=512
#define D2 128
#define MAXB 64
#define MAXN 4096

// Scratch (no cudaMalloc allowed)
__device__ float g_q[MAXB * D2];          // 32 KB
__device__ float g_logits[MAXB * MAXN];   // 1 MB

// ---------------------------------------------------------------------------
// K1: q[b,d] = sum_e yq[b,e] * w[e,d]
// grid = B, block = (128, 4): threadIdx.x = d, threadIdx.y = e-slice.
// Each thread sums 32 e-values with a fully unrolled loop (high MLP),
// then 4 partials are reduced through shared memory.
// ---------------------------------------------------------------------------
__global__ __launch_bounds__(512) void qproj_kernel(const float* __restrict__ yq,
                                                    const float* __restrict__ w) {
    __shared__ float syq[D2];
    __shared__ float part[4][D2];
    const int b = blockIdx.x;
    const int d = threadIdx.x;     // 0..127
    const int k = threadIdx.y;     // 0..3
    if (k == 0) syq[d] = yq[b * D2 + d];
    __syncthreads();

    float acc = 0.f;
    const int e0 = k * 32;
#pragma unroll
    for (int j = 0; j < 32; j++) {
        acc = fmaf(syq[e0 + j], w[(e0 + j) * D2 + d], acc);
    }
    part[k][d] = acc;
    __syncthreads();
    if (k == 0) {
        g_q[b * D2 + d] = part[0][d] + part[1][d] + part[2][d] + part[3][d];
    }
}

// ---------------------------------------------------------------------------
// K2: logits[b,n] = q[b] . y_past[b,n]
// One warp handles 8 consecutive rows; each lane reads one float4 per row
// (512B contiguous per warp per row). 8 front-batched independent loads
// per thread -> MLP 8. Block = 512 threads = 16 warps = 128 rows.
// grid = (N/128, B)
// ---------------------------------------------------------------------------
__global__ __launch_bounds__(512) void logits_kernel(const float* __restrict__ y_past, int N) {
    const int b = blockIdx.y;
    __shared__ float sq[D2];
    if (threadIdx.x < D2) sq[threadIdx.x] = g_q[b * D2 + threadIdx.x];
    __syncthreads();

    const int warp = threadIdx.x >> 5;
    const int lane = threadIdx.x & 31;
    const int row0 = blockIdx.x * 128 + warp * 8;

    const float4* __restrict__ base =
        reinterpret_cast<const float4*>(y_past + (size_t)b * N * D2);
    const float4 qv = reinterpret_cast<const float4*>(sq)[lane];

    // Front-batch 8 independent row loads for MLP
    float4 v0 = base[(size_t)(row0 + 0) * 32 + lane];
    float4 v1 = base[(size_t)(row0 + 1) * 32 + lane];
    float4 v2 = base[(size_t)(row0 + 2) * 32 + lane];
    float4 v3 = base[(size_t)(row0 + 3) * 32 + lane];
    float4 v4 = base[(size_t)(row0 + 4) * 32 + lane];
    float4 v5 = base[(size_t)(row0 + 5) * 32 + lane];
    float4 v6 = base[(size_t)(row0 + 6) * 32 + lane];
    float4 v7 = base[(size_t)(row0 + 7) * 32 + lane];

    float a0 = fmaf(v0.x, qv.x, fmaf(v0.y, qv.y, fmaf(v0.z, qv.z, v0.w * qv.w)));
    float a1 = fmaf(v1.x, qv.x, fmaf(v1.y, qv.y, fmaf(v1.z, qv.z, v1.w * qv.w)));
    float a2 = fmaf(v2.x, qv.x, fmaf(v2.y, qv.y, fmaf(v2.z, qv.z, v2.w * qv.w)));
    float a3 = fmaf(v3.x, qv.x, fmaf(v3.y, qv.y, fmaf(v3.z, qv.z, v3.w * qv.w)));
    float a4 = fmaf(v4.x, qv.x, fmaf(v4.y, qv.y, fmaf(v4.z, qv.z, v4.w * qv.w)));
    float a5 = fmaf(v5.x, qv.x, fmaf(v5.y, qv.y, fmaf(v5.z, qv.z, v5.w * qv.w)));
    float a6 = fmaf(v6.x, qv.x, fmaf(v6.y, qv.y, fmaf(v6.z, qv.z, v6.w * qv.w)));
    float a7 = fmaf(v7.x, qv.x, fmaf(v7.y, qv.y, fmaf(v7.z, qv.z, v7.w * qv.w)));

#pragma unroll
    for (int o = 16; o; o >>= 1) {
        a0 += __shfl_xor_sync(0xffffffffu, a0, o);
        a1 += __shfl_xor_sync(0xffffffffu, a1, o);
        a2 += __shfl_xor_sync(0xffffffffu, a2, o);
        a3 += __shfl_xor_sync(0xffffffffu, a3, o);
        a4 += __shfl_xor_sync(0xffffffffu, a4, o);
        a5 += __shfl_xor_sync(0xffffffffu, a5, o);
        a6 += __shfl_xor_sync(0xffffffffu, a6, o);
        a7 += __shfl_xor_sync(0xffffffffu, a7, o);
    }
    if (lane == 0) {
        float4* dst = reinterpret_cast<float4*>(g_logits + (size_t)b * N + row0);
        dst[0] = make_float4(a0, a1, a2, a3);
        dst[1] = make_float4(a4, a5, a6, a7);
    }
}

// ---------------------------------------------------------------------------
// K3: per-batch softmax over N logits + scatter-add into S bins, normalize.
// grid = B, block = 1024, dynamic smem = S floats (bins)
// ---------------------------------------------------------------------------
__global__ __launch_bounds__(1024) void softmax_scatter_kernel(const int* __restrict__ s_past,
                                                               float* __restrict__ out,
                                                               int N, int S) {
    extern __shared__ float bins[];          // S floats
    __shared__ float red[32];
    __shared__ float bcast;

    const int b = blockIdx.x;
    const int t = threadIdx.x;
    const int T = blockDim.x;                // 1024
    const int per = N / T;                   // 4

    // Zero bins
    for (int s = t; s < S; s += T) bins[s] = 0.f;

    // Front-batch ALL loads (logits + s_past) so the DRAM gather of s_past
    // overlaps the max-reduction work.
    float vals[8];
    int   sid[8];
    float mx = -CUDART_INF_F;
#pragma unroll 4
    for (int i = 0; i < per; i++) {
        vals[i] = g_logits[(size_t)b * N + t + i * T];
        sid[i]  = s_past[(size_t)b * N + t + i * T];
    }
#pragma unroll 4
    for (int i = 0; i < per; i++) mx = fmaxf(mx, vals[i]);

    // block-reduce max
#pragma unroll
    for (int o = 16; o; o >>= 1) mx = fmaxf(mx, __shfl_xor_sync(0xffffffffu, mx, o));
    if ((t & 31) == 0) red[t >> 5] = mx;
    __syncthreads();
    if (t < 32) {
        float m = (t < T / 32) ? red[t] : -CUDART_INF_F;
#pragma unroll
        for (int o = 16; o; o >>= 1) m = fmaxf(m, __shfl_xor_sync(0xffffffffu, m, o));
        if (t == 0) bcast = m;
    }
    __syncthreads();
    mx = bcast;

    // exp, local sum, scatter into shared bins
    float sum = 0.f;
#pragma unroll 4
    for (int i = 0; i < per; i++) {
        float e = __expf(vals[i] - mx);
        sum += e;
        atomicAdd(&bins[sid[i]], e);
    }
    __syncthreads();   // orders bin writes before the read below

    // block-reduce sum
#pragma unroll
    for (int o = 16; o; o >>= 1) sum += __shfl_xor_sync(0xffffffffu, sum, o);
    if ((t & 31) == 0) red[t >> 5] = sum;
    __syncthreads();
    if (t < 32) {
        float s2 = (t < T / 32) ? red[t] : 0.f;
#pragma unroll
        for (int o = 16; o; o >>= 1) s2 += __shfl_xor_sync(0xffffffffu, s2, o);
        if (t == 0) bcast = s2;
    }
    __syncthreads();
    const float inv_z = 1.0f / bcast;

    for (int s = t; s < S; s += T) {
        out[(size_t)b * S + s] = bins[s] * inv_z;
    }
}

// ---------------------------------------------------------------------------
// kernel_launch
// Inputs (metadata order): s_past (int32, B*N), yq (f32, B*D2),
//                          y_past (f32, B*N*D2), w_mat (f32, D2*D2),
//                          size_s (int scalar, on device)
// Output: post_est (f32, B*S)
// ---------------------------------------------------------------------------
extern "C" void kernel_launch(void* const* d_in, const int* in_sizes, int n_in,
                              void* d_out, int out_size) {
    const int*   s_past = (const int*)d_in[0];
    const float* yq     = (const float*)d_in[1];
    const float* y_past = (const float*)d_in[2];
    const float* w_mat  = (const float*)d_in[3];
    float*       out    = (float*)d_out;

    const int D = D2;                       // 128 (w_mat is D2 x D2)
    const int B = in_sizes[1] / D;          // 64
    const int N = in_sizes[0] / B;          // 4096
    const int S = out_size / B;             // 512

    qproj_kernel<<<B, dim3(D, 4)>>>(yq, w_mat);

    dim3 grid2(N / 128, B);
    logits_kernel<<<grid2, 512>>>(y_past, N);

    softmax_scatter_kernel<<<B, 1024, S * sizeof(float)>>>(s_past, out, N, S);
}

// round 4
// speedup vs baseline: 1.2551x; 1.0010x over previous
#include <cuda_runtime.h>
#include <math_constants.h>

// Problem shape (fixed by the dataset): B=64, N=4096, D2=128, S=512
#define D2 128
#define MAXB 64
#define MAXN 4096
#define ECH 8          // e-chunks for qproj

// Scratch (no cudaMalloc allowed)
__device__ float g_qpart[ECH][MAXB * D2];   // 8 partial q arrays (256 KB)
__device__ float g_logits[MAXB * MAXN];     // 1 MB

// ---------------------------------------------------------------------------
// K1: partial q: g_qpart[c][b,d] = sum_{e in chunk c} yq[b,e] * w[e,d]
// grid = (B, ECH), block = 128. Each thread: 16 independent LDG+FMA.
// 512 blocks -> all SMs busy, DRAM latency chains overlap across blocks.
// Final 8-way reduction is folded into K2's q load.
// ---------------------------------------------------------------------------
__global__ __launch_bounds__(128) void qproj_kernel(const float* __restrict__ yq,
                                                    const float* __restrict__ w) {
    const int b = blockIdx.x;
    const int c = blockIdx.y;
    const int d = threadIdx.x;     // 0..127
    __shared__ float syq[D2 / ECH];    // 16
    if (d < D2 / ECH) syq[d] = yq[b * D2 + c * (D2 / ECH) + d];
    __syncthreads();

    const int e0 = c * (D2 / ECH);
    float acc = 0.f;
#pragma unroll
    for (int j = 0; j < D2 / ECH; j++) {
        acc = fmaf(syq[j], w[(e0 + j) * D2 + d], acc);
    }
    g_qpart[c][b * D2 + d] = acc;
}

// ---------------------------------------------------------------------------
// K2: logits[b,n] = q[b] . y_past[b,n]
// One warp handles 8 consecutive rows; each lane reads one float4 per row
// (512B contiguous per warp per row), streaming (evict-first) loads.
// Block = 512 threads = 16 warps = 128 rows. grid = (N/128, B).
// ---------------------------------------------------------------------------
__global__ __launch_bounds__(512) void logits_kernel(const float* __restrict__ y_past, int N) {
    const int b = blockIdx.y;
    __shared__ float sq[D2];
    if (threadIdx.x < D2) {
        float s = 0.f;
#pragma unroll
        for (int p = 0; p < ECH; p++) s += g_qpart[p][b * D2 + threadIdx.x];
        sq[threadIdx.x] = s;
    }
    __syncthreads();

    const int warp = threadIdx.x >> 5;
    const int lane = threadIdx.x & 31;
    const int row0 = blockIdx.x * 128 + warp * 8;

    const float4* __restrict__ base =
        reinterpret_cast<const float4*>(y_past + (size_t)b * N * D2);
    const float4 qv = reinterpret_cast<const float4*>(sq)[lane];

    // Front-batch 8 independent streaming row loads for MLP
    float4 v0 = __ldcs(&base[(size_t)(row0 + 0) * 32 + lane]);
    float4 v1 = __ldcs(&base[(size_t)(row0 + 1) * 32 + lane]);
    float4 v2 = __ldcs(&base[(size_t)(row0 + 2) * 32 + lane]);
    float4 v3 = __ldcs(&base[(size_t)(row0 + 3) * 32 + lane]);
    float4 v4 = __ldcs(&base[(size_t)(row0 + 4) * 32 + lane]);
    float4 v5 = __ldcs(&base[(size_t)(row0 + 5) * 32 + lane]);
    float4 v6 = __ldcs(&base[(size_t)(row0 + 6) * 32 + lane]);
    float4 v7 = __ldcs(&base[(size_t)(row0 + 7) * 32 + lane]);

    float a0 = fmaf(v0.x, qv.x, fmaf(v0.y, qv.y, fmaf(v0.z, qv.z, v0.w * qv.w)));
    float a1 = fmaf(v1.x, qv.x, fmaf(v1.y, qv.y, fmaf(v1.z, qv.z, v1.w * qv.w)));
    float a2 = fmaf(v2.x, qv.x, fmaf(v2.y, qv.y, fmaf(v2.z, qv.z, v2.w * qv.w)));
    float a3 = fmaf(v3.x, qv.x, fmaf(v3.y, qv.y, fmaf(v3.z, qv.z, v3.w * qv.w)));
    float a4 = fmaf(v4.x, qv.x, fmaf(v4.y, qv.y, fmaf(v4.z, qv.z, v4.w * qv.w)));
    float a5 = fmaf(v5.x, qv.x, fmaf(v5.y, qv.y, fmaf(v5.z, qv.z, v5.w * qv.w)));
    float a6 = fmaf(v6.x, qv.x, fmaf(v6.y, qv.y, fmaf(v6.z, qv.z, v6.w * qv.w)));
    float a7 = fmaf(v7.x, qv.x, fmaf(v7.y, qv.y, fmaf(v7.z, qv.z, v7.w * qv.w)));

#pragma unroll
    for (int o = 16; o; o >>= 1) {
        a0 += __shfl_xor_sync(0xffffffffu, a0, o);
        a1 += __shfl_xor_sync(0xffffffffu, a1, o);
        a2 += __shfl_xor_sync(0xffffffffu, a2, o);
        a3 += __shfl_xor_sync(0xffffffffu, a3, o);
        a4 += __shfl_xor_sync(0xffffffffu, a4, o);
        a5 += __shfl_xor_sync(0xffffffffu, a5, o);
        a6 += __shfl_xor_sync(0xffffffffu, a6, o);
        a7 += __shfl_xor_sync(0xffffffffu, a7, o);
    }
    if (lane == 0) {
        float4* dst = reinterpret_cast<float4*>(g_logits + (size_t)b * N + row0);
        dst[0] = make_float4(a0, a1, a2, a3);
        dst[1] = make_float4(a4, a5, a6, a7);
    }
}

// ---------------------------------------------------------------------------
// K3: per-batch softmax over N logits + scatter-add into S bins, normalize.
// grid = B, block = 1024, dynamic smem = S floats (bins)
// ---------------------------------------------------------------------------
__global__ __launch_bounds__(1024) void softmax_scatter_kernel(const int* __restrict__ s_past,
                                                               float* __restrict__ out,
                                                               int N, int S) {
    extern __shared__ float bins[];          // S floats
    __shared__ float red[32];
    __shared__ float bcast;

    const int b = blockIdx.x;
    const int t = threadIdx.x;
    const int T = blockDim.x;                // 1024
    const int per = N / T;                   // 4

    // Zero bins
    for (int s = t; s < S; s += T) bins[s] = 0.f;

    // Front-batch ALL loads (logits L2-hot + s_past DRAM gather)
    float vals[8];
    int   sid[8];
    float mx = -CUDART_INF_F;
#pragma unroll 4
    for (int i = 0; i < per; i++) {
        vals[i] = g_logits[(size_t)b * N + t + i * T];
        sid[i]  = __ldcs(&s_past[(size_t)b * N + t + i * T]);
    }
#pragma unroll 4
    for (int i = 0; i < per; i++) mx = fmaxf(mx, vals[i]);

    // block-reduce max
#pragma unroll
    for (int o = 16; o; o >>= 1) mx = fmaxf(mx, __shfl_xor_sync(0xffffffffu, mx, o));
    if ((t & 31) == 0) red[t >> 5] = mx;
    __syncthreads();
    if (t < 32) {
        float m = (t < T / 32) ? red[t] : -CUDART_INF_F;
#pragma unroll
        for (int o = 16; o; o >>= 1) m = fmaxf(m, __shfl_xor_sync(0xffffffffu, m, o));
        if (t == 0) bcast = m;
    }
    __syncthreads();
    mx = bcast;

    // exp, local sum, scatter into shared bins
    float sum = 0.f;
#pragma unroll 4
    for (int i = 0; i < per; i++) {
        float e = __expf(vals[i] - mx);
        sum += e;
        atomicAdd(&bins[sid[i]], e);
    }
    __syncthreads();   // orders bin writes before the read below

    // block-reduce sum
#pragma unroll
    for (int o = 16; o; o >>= 1) sum += __shfl_xor_sync(0xffffffffu, sum, o);
    if ((t & 31) == 0) red[t >> 5] = sum;
    __syncthreads();
    if (t < 32) {
        float s2 = (t < T / 32) ? red[t] : 0.f;
#pragma unroll
        for (int o = 16; o; o >>= 1) s2 += __shfl_xor_sync(0xffffffffu, s2, o);
        if (t == 0) bcast = s2;
    }
    __syncthreads();
    const float inv_z = 1.0f / bcast;

    for (int s = t; s < S; s += T) {
        out[(size_t)b * S + s] = bins[s] * inv_z;
    }
}

// ---------------------------------------------------------------------------
// kernel_launch
// Inputs (metadata order): s_past (int32, B*N), yq (f32, B*D2),
//                          y_past (f32, B*N*D2), w_mat (f32, D2*D2),
//                          size_s (int scalar, on device)
// Output: post_est (f32, B*S)
// ---------------------------------------------------------------------------
extern "C" void kernel_launch(void* const* d_in, const int* in_sizes, int n_in,
                              void* d_out, int out_size) {
    const int*   s_past = (const int*)d_in[0];
    const float* yq     = (const float*)d_in[1];
    const float* y_past = (const float*)d_in[2];
    const float* w_mat  = (const float*)d_in[3];
    float*       out    = (float*)d_out;

    const int D = D2;                       // 128 (w_mat is D2 x D2)
    const int B = in_sizes[1] / D;          // 64
    const int N = in_sizes[0] / B;          // 4096
    const int S = out_size / B;             // 512

    qproj_kernel<<<dim3(B, ECH), D>>>(yq, w_mat);

    dim3 grid2(N / 128, B);
    logits_kernel<<<grid2, 512>>>(y_past, N);

    softmax_scatter_kernel<<<B, 1024, S * sizeof(float)>>>(s_past, out, N, S);
}